// round 6
// baseline (speedup 1.0000x reference)
#include <cuda_runtime.h>
#include <cstdint>

#define B_SIZE 4096
#define T_LEN  2048
#define H_DIM  32
#define THREADS 128
#define WARPS  (THREADS/32)
#define GRID   456

typedef unsigned long long ull;

__device__ int g_task_counter;
__device__ int g_order[B_SIZE];

// ---- packed f32x2 helpers ----
__device__ __forceinline__ ull pk2(float a, float b) {
    ull r; asm("mov.b64 %0, {%1, %2};" : "=l"(r) : "f"(a), "f"(b)); return r;
}
__device__ __forceinline__ void upk2(ull v, float& a, float& b) {
    asm("mov.b64 {%0, %1}, %2;" : "=f"(a), "=f"(b) : "l"(v));
}
__device__ __forceinline__ void ffma2(ull& d, ull a, ull b) {
    asm("fma.rn.f32x2 %0, %1, %2, %0;" : "+l"(d) : "l"(a), "l"(b));
}

// ---- fast transcendentals (MUFU) ----
__device__ __forceinline__ float ex2f(float x) {
    float r; asm("ex2.approx.f32 %0, %1;" : "=f"(r) : "f"(x)); return r;
}
__device__ __forceinline__ float rcpf(float x) {
    float r; asm("rcp.approx.f32 %0, %1;" : "=f"(r) : "f"(x)); return r;
}
#define L2E 1.4426950408889634f

// sigmoid(a0+a1) with the horizontal reduce fused into the exponent argument
__device__ __forceinline__ float sig2(float a0, float a1) {
    return rcpf(1.f + ex2f(fmaf(-L2E, a0, -L2E * a1)));
}
// tanh(a0+a1), reduce fused
__device__ __forceinline__ float tanh2(float a0, float a1) {
    return fmaf(-2.f, rcpf(1.f + ex2f(fmaf(2.f * L2E, a0, 2.f * L2E * a1))), 1.f);
}
__device__ __forceinline__ float sigf(float z)  { return rcpf(1.f + ex2f(-L2E * z)); }
__device__ __forceinline__ float tanhf_(float z){ return fmaf(-2.f, rcpf(1.f + ex2f(2.f * L2E * z)), 1.f); }

// ---- LPT scheduler: order tasks longest-first (16-step buckets) ----
__global__ void __launch_bounds__(128)
schedule_kernel(const int* __restrict__ lengths)
{
    __shared__ int s_hist[128];
    __shared__ int s_base[128];
    const int tid = threadIdx.x;
    s_hist[tid] = 0;
    __syncthreads();
    for (int i = tid; i < B_SIZE; i += 128) {
        int b = (T_LEN - lengths[i]) >> 4;   // bucket 0 = longest
        atomicAdd(&s_hist[b], 1);
    }
    __syncthreads();
    if (tid == 0) {
        int acc = 0;
        for (int b = 0; b < 128; b++) { s_base[b] = acc; acc += s_hist[b]; }
        g_task_counter = 0;
    }
    __syncthreads();
    s_hist[tid] = 0;
    __syncthreads();
    for (int i = tid; i < B_SIZE; i += 128) {
        int b = (T_LEN - lengths[i]) >> 4;
        int pos = s_base[b] + atomicAdd(&s_hist[b], 1);
        g_order[pos] = i;
    }
}

__global__ void __launch_bounds__(THREADS, 3)
bilstm_kernel(const float* __restrict__ x,
              const int*   __restrict__ lengths,
              const float* __restrict__ w_ih,
              const float* __restrict__ w_hh,
              const float* __restrict__ b_ih,
              const float* __restrict__ b_hh,
              const float* __restrict__ fc_w,
              const float* __restrict__ fc_b,
              const float* __restrict__ fc2_w,
              const float* __restrict__ fc2_b,
              float* __restrict__ out)
{
    const int lane = threadIdx.x & 31;

    // ---- per-lane recurrent weights in registers (loaded once) ----
    const int l = lane;
    const float bci = b_ih[l]      + b_hh[l];
    const float bcf = b_ih[32 + l] + b_hh[32 + l];
    const float bcg = b_ih[64 + l] + b_hh[64 + l];
    const float bco = b_ih[96 + l] + b_hh[96 + l];
    const float wxi = w_ih[l], wxf = w_ih[32 + l], wxg = w_ih[64 + l], wxo = w_ih[96 + l];

    ull wI[16], wF[16], wG[16], wO[16];
    {
        const ull* pI = (const ull*)(w_hh + (0  + l) * H_DIM);
        const ull* pF = (const ull*)(w_hh + (32 + l) * H_DIM);
        const ull* pG = (const ull*)(w_hh + (64 + l) * H_DIM);
        const ull* pO = (const ull*)(w_hh + (96 + l) * H_DIM);
        #pragma unroll
        for (int j = 0; j < 16; j++) { wI[j] = pI[j]; wF[j] = pF[j]; wG[j] = pG[j]; wO[j] = pO[j]; }
    }

    // ---- dynamic task loop: one warp = one sequence at a time (LPT order) ----
    for (;;) {
        unsigned tk = 0;
        if (lane == 0) tk = (unsigned)atomicAdd(&g_task_counter, 1);
        tk = __shfl_sync(0xffffffffu, tk, 0);
        if (tk >= B_SIZE) break;
        const int task = g_order[tk];

        const int len = lengths[task];
        const float* xb = x + (size_t)task * T_LEN;

        float c  = 0.f;
        float hn = 0.f;          // h for this lane's unit; broadcast via shfl

        int t = len - 1;
        float xv = __ldg(xb + t);
        while (t >= 0) {
            const int tn = (t > 0) ? (t - 1) : 0;
            float xn = __ldg(xb + tn);   // prefetch next x off the critical chain

            // gate accumulators: (even-k partial, odd-k partial)
            ull ai = pk2(fmaf(xv, wxi, bci), 0.f);
            ull af = pk2(fmaf(xv, wxf, bcf), 0.f);
            ull ag = pk2(fmaf(xv, wxg, bcg), 0.f);
            ull ao = pk2(fmaf(xv, wxo, bco), 0.f);

            // h broadcast via shuffles (no smem, no barrier), fused into matvec
            #pragma unroll
            for (int j = 0; j < 16; j++) {
                const float ha = __shfl_sync(0xffffffffu, hn, 2 * j);
                const float hb = __shfl_sync(0xffffffffu, hn, 2 * j + 1);
                const ull  q  = pk2(ha, hb);
                ffma2(ai, wI[j], q);
                ffma2(af, wF[j], q);
                ffma2(ag, wG[j], q);
                ffma2(ao, wO[j], q);
            }
            float e0, e1, f0, f1, g0, g1, o0, o1;
            upk2(ai, e0, e1);
            upk2(af, f0, f1);
            upk2(ag, g0, g1);
            upk2(ao, o0, o1);

            const float iv = sig2(e0, e1);
            const float fv = sig2(f0, f1);
            const float gv = tanh2(g0, g1);
            const float ov = sig2(o0, o1);
            c  = fmaf(fv, c, iv * gv);
            hn = ov * tanhf_(c);

            xv = xn;
            --t;
        }

        // ---- FC head (cold path; h gathered via shuffles) ----
        {
            float u0 = __ldg(fc_b + lane);
            float u1 = __ldg(fc_b + 32 + lane);
            #pragma unroll
            for (int k = 0; k < 32; k++) {
                const float hk = __shfl_sync(0xffffffffu, hn, k);
                u0 = fmaf(__ldg(fc_w + lane * 32 + k),        hk, u0);
                u1 = fmaf(__ldg(fc_w + (32 + lane) * 32 + k), hk, u1);
            }
            u0 = (u0 > 0.f) ? u0 : (ex2f(L2E * u0) - 1.f);
            u1 = (u1 > 0.f) ? u1 : (ex2f(L2E * u1) - 1.f);

            float part = u0 * __ldg(fc2_w + lane) + u1 * __ldg(fc2_w + 32 + lane);
            #pragma unroll
            for (int s = 16; s; s >>= 1) part += __shfl_xor_sync(0xffffffffu, part, s);
            if (lane == 0) out[task] = sigf(part + __ldg(fc2_b));
        }
    }
}

extern "C" void kernel_launch(void* const* d_in, const int* in_sizes, int n_in,
                              void* d_out, int out_size)
{
    const float* x       = (const float*)d_in[0];
    const int*   lengths = (const int*)  d_in[1];
    const float* w_ih    = (const float*)d_in[2];
    const float* w_hh    = (const float*)d_in[3];
    const float* b_ih    = (const float*)d_in[4];
    const float* b_hh    = (const float*)d_in[5];
    const float* fc_w    = (const float*)d_in[6];
    const float* fc_b    = (const float*)d_in[7];
    const float* fc2_w   = (const float*)d_in[8];
    const float* fc2_b   = (const float*)d_in[9];
    float* out = (float*)d_out;

    schedule_kernel<<<1, 128>>>(lengths);
    bilstm_kernel<<<GRID, THREADS>>>(x, lengths, w_ih, w_hh, b_ih, b_hh,
                                     fc_w, fc_b, fc2_w, fc2_b, out);
}